// round 10
// baseline (speedup 1.0000x reference)
#include <cuda_runtime.h>
#include <cstdint>

#define NN 65536
#define NE 1048576
typedef unsigned long long u64;
typedef long long ll;

// ------------------- device scratch (no allocation allowed) -------------------
__device__ __align__(16) float g_h  [(size_t)NN * 128];
__device__ __align__(16) float g_h2 [(size_t)NN * 128];
__device__ __align__(16) float g_agg[(size_t)NN * 128];
__device__ __align__(16) float g_xw [(size_t)NN * 512];
__device__ float g_dinv[NN];
__device__ float g_bias[512];
__device__ int   g_cnt[NN];
__device__ int   g_cur[NN];
__device__ int   g_indptr[NN + 1];
__device__ __align__(16) int2 g_csr[NE];
__device__ int   g_e32;       // 1 if edge_index is really int32

// ------------------- packed f32x2 helpers -------------------
__device__ __forceinline__ u64 pk2(float x, float y) {
    u64 r; asm("mov.b64 %0,{%1,%2};" : "=l"(r) : "f"(x), "f"(y)); return r;
}
__device__ __forceinline__ u64 pkdup(float x) {
    u64 r; asm("mov.b64 %0,{%1,%1};" : "=l"(r) : "f"(x)); return r;
}
__device__ __forceinline__ void fma2(u64 &d, u64 a, u64 b) {
    asm("fma.rn.f32x2 %0,%1,%2,%0;" : "+l"(d) : "l"(a), "l"(b));
}
__device__ __forceinline__ u64 add2(u64 a, u64 b) {
    u64 r; asm("add.rn.f32x2 %0,%1,%2;" : "=l"(r) : "l"(a), "l"(b)); return r;
}
__device__ __forceinline__ float2 up2(u64 v) {
    float2 r; asm("mov.b64 {%0,%1},%2;" : "=f"(r.x), "=f"(r.y) : "l"(v)); return r;
}

// ------------------- prep: zero + bias + dtype detect -------------------
__global__ __launch_bounds__(1024) void k_prep(const float* __restrict__ bi,
                                               const float* __restrict__ bh,
                                               const ll* __restrict__ ei) {
    int i = blockIdx.x * 1024 + threadIdx.x;
    if (i < NN) g_cnt[i] = 0;
    if (i < 512) g_bias[i] = bi[i] + bh[i];
    if (i == 0) {
        int bad = 0;
        for (int j = 0; j < 64; j++) {
            ll v = ei[j];
            if (v < 0 || v >= NN) bad = 1;
        }
        g_e32 = bad;
    }
}
__global__ __launch_bounds__(256) void k_hist(const ll* __restrict__ ei) {
    int e = blockIdx.x * 256 + threadIdx.x;
    if (e >= NE) return;
    int dst = g_e32 ? ((const int*)ei)[NE + e] : (int)ei[NE + e];
    atomicAdd(&g_cnt[dst], 1);
}
// scan + rsqrt fused (single block)
__global__ __launch_bounds__(1024) void k_scan() {
    __shared__ int ssum[1024];
    int t = threadIdx.x;
    int base = t * 64;
    int s = 0;
    const int4* c4 = (const int4*)&g_cnt[base];
    for (int i = 0; i < 16; i++) {
        int4 v = c4[i];
        s += v.x + v.y + v.z + v.w;
    }
    ssum[t] = s;
    __syncthreads();
    for (int off = 1; off < 1024; off <<= 1) {
        int add = (t >= off) ? ssum[t - off] : 0;
        __syncthreads();
        ssum[t] += add;
        __syncthreads();
    }
    int run = ssum[t] - s;   // exclusive prefix of this chunk
    for (int i = 0; i < 64; i++) {
        int c = g_cnt[base + i];
        g_indptr[base + i] = run;
        g_cur[base + i]    = run;
        g_dinv[base + i]   = rsqrtf(1.0f + (float)c);
        run += c;
    }
    if (t == 1023) g_indptr[NN] = run;
}
__global__ __launch_bounds__(256) void k_scatter(const ll* __restrict__ ei) {
    int e = blockIdx.x * 256 + threadIdx.x;
    if (e >= NE) return;
    int src, dst;
    if (g_e32) {
        const int* p = (const int*)ei;
        src = p[e]; dst = p[NE + e];
    } else {
        src = (int)ei[e]; dst = (int)ei[NE + e];
    }
    int pos = atomicAdd(&g_cur[dst], 1);
    float nm = g_dinv[src] * g_dinv[dst];
    g_csr[pos] = make_int2(src, __float_as_int(nm));
}

// ------------------- tiled GEMM (packed f32x2) -------------------
// MODE 0: g_h = x @ W1        (fused: g_agg = g_h * dinv^2)
// MODE 1: g_h = g_h2 @ W2     (same fusion)
// MODE 2: g_xw = g_h2 @ W_ih^T + (b_ih + b_hh)
template<int MODE>
__global__ __launch_bounds__(256)
void k_gemm(const float* __restrict__ Aext, const float* __restrict__ B)
{
    extern __shared__ float sm[];
    float* sB = sm;               // [128][132]  sB[k][n]
    float* sA = sm + 128 * 132;   // [128][132]  sA[k][r]  (A transposed)
    const float* A = (MODE == 0) ? Aext : g_h2;
    const int t = threadIdx.x;
    const int row0 = blockIdx.x * 128;
    const int col0 = (MODE == 2) ? blockIdx.y * 128 : 0;

    for (int idx = t; idx < 128 * 32; idx += 256) {
        int r = idx >> 5, k4 = idx & 31;
        float4 v = *(const float4*)&A[(size_t)(row0 + r) * 128 + k4 * 4];
        sA[(k4 * 4 + 0) * 132 + r] = v.x;
        sA[(k4 * 4 + 1) * 132 + r] = v.y;
        sA[(k4 * 4 + 2) * 132 + r] = v.z;
        sA[(k4 * 4 + 3) * 132 + r] = v.w;
    }
    if (MODE != 2) {
        for (int idx = t; idx < 128 * 32; idx += 256) {
            int k = idx >> 5, n4 = idx & 31;
            *(float4*)&sB[k * 132 + n4 * 4] = *(const float4*)&B[(size_t)k * 128 + n4 * 4];
        }
    } else {
        for (int idx = t; idx < 128 * 32; idx += 256) {
            int n = idx >> 5, k4 = idx & 31;
            float4 v = *(const float4*)&B[(size_t)(col0 + n) * 128 + k4 * 4];
            sB[(k4 * 4 + 0) * 132 + n] = v.x;
            sB[(k4 * 4 + 1) * 132 + n] = v.y;
            sB[(k4 * 4 + 2) * 132 + n] = v.z;
            sB[(k4 * 4 + 3) * 132 + n] = v.w;
        }
    }
    __syncthreads();

    const int warp = t >> 5, lane = t & 31;
    const int r0 = warp * 16;
    const int c0 = lane * 4;
    u64 acc[8][4];
#pragma unroll
    for (int i = 0; i < 8; i++)
#pragma unroll
        for (int c = 0; c < 4; c++) acc[i][c] = 0ull;

    for (int k = 0; k < 128; k++) {
        float4 bv = *(const float4*)&sB[k * 132 + c0];
        u64 b0 = pkdup(bv.x), b1 = pkdup(bv.y), b2 = pkdup(bv.z), b3 = pkdup(bv.w);
        const u64* ap = (const u64*)&sA[k * 132 + r0];
#pragma unroll
        for (int ii = 0; ii < 8; ii++) {
            u64 a = ap[ii];
            fma2(acc[ii][0], a, b0);
            fma2(acc[ii][1], a, b1);
            fma2(acc[ii][2], a, b2);
            fma2(acc[ii][3], a, b3);
        }
    }

    float4 bb = make_float4(0.f, 0.f, 0.f, 0.f);
    if (MODE == 2) bb = *(const float4*)&g_bias[col0 + c0];
#pragma unroll
    for (int ii = 0; ii < 8; ii++) {
        float2 u0 = up2(acc[ii][0]), u1 = up2(acc[ii][1]);
        float2 u2 = up2(acc[ii][2]), u3 = up2(acc[ii][3]);
        int rA = row0 + r0 + 2 * ii;
        float4 v0 = make_float4(u0.x + bb.x, u1.x + bb.y, u2.x + bb.z, u3.x + bb.w);
        float4 v1 = make_float4(u0.y + bb.x, u1.y + bb.y, u2.y + bb.z, u3.y + bb.w);
        if (MODE == 2) {
            *(float4*)&g_xw[(size_t)rA * 512 + col0 + c0] = v0;
            *(float4*)&g_xw[(size_t)(rA + 1) * 512 + col0 + c0] = v1;
        } else {
            *(float4*)&g_h[(size_t)rA * 128 + c0] = v0;
            *(float4*)&g_h[(size_t)(rA + 1) * 128 + c0] = v1;
            float d0 = g_dinv[rA];     float s0 = d0 * d0;
            float d1 = g_dinv[rA + 1]; float s1 = d1 * d1;
            float4 w0 = make_float4(v0.x * s0, v0.y * s0, v0.z * s0, v0.w * s0);
            float4 w1 = make_float4(v1.x * s1, v1.y * s1, v1.z * s1, v1.w * s1);
            *(float4*)&g_agg[(size_t)rA * 128 + c0] = w0;
            *(float4*)&g_agg[(size_t)(rA + 1) * 128 + c0] = w1;
        }
    }
}

// ------------------- edge aggregation: warp per node -------------------
__global__ __launch_bounds__(256)
void k_agg(const float* __restrict__ bias)
{
    int node = blockIdx.x * 8 + (threadIdx.x >> 5);
    if (node >= NN) return;
    int lane = threadIdx.x & 31;
    int s0 = g_indptr[node], s1 = g_indptr[node + 1];
    float4 acc = *(const float4*)&g_agg[(size_t)node * 128 + lane * 4];

    for (int e = s0; e < s1; e++) {
        int2 cur = __ldg(&g_csr[e]);
        float4 hv = __ldg((const float4*)&g_h[(size_t)cur.x * 128 + lane * 4]);
        float nm = __int_as_float(cur.y);
        acc.x += hv.x * nm; acc.y += hv.y * nm;
        acc.z += hv.z * nm; acc.w += hv.w * nm;
    }
    float4 bb = *(const float4*)&bias[lane * 4];
    float4 o;
    o.x = fmaxf(acc.x + bb.x, 0.f);
    o.y = fmaxf(acc.y + bb.y, 0.f);
    o.z = fmaxf(acc.z + bb.z, 0.f);
    o.w = fmaxf(acc.w + bb.w, 0.f);
    *(float4*)&g_h2[(size_t)node * 128 + lane * 4] = o;
}

// ------------------- LSTM: one CTA per batch, shuffle gate exchange -------------------
// Thread t -> unit j = t>>1. Even t owns rows j (i) and 128+j (f);
// odd t owns rows 256+j (g) and 384+j (o).  rowA = (t&1)*256 + j, rowB = rowA+128.
// rowA: all 128 weights in regs. rowB: k<64 in regs, k in [64,128) in smem
// (circular chunk swizzle, conflict-free LDS.128). h read via broadcast LDS.128.
// Odd lanes compute their own activations (tanh(g), sigm(o)); shuffles carry
// activated values; even lanes finish c/h. ONE barrier per step.
__device__ __forceinline__ float sigmf_(float x) {
    return __fdividef(1.0f, 1.0f + __expf(-x));
}
__device__ __forceinline__ float tanhf_(float x) {
    float e = __expf(-2.0f * fabsf(x));            // in (0,1], no overflow
    return copysignf(__fdividef(1.0f - e, 1.0f + e), x);
}

__global__ __launch_bounds__(256, 1)
void k_lstm(const float* __restrict__ Whh, float* __restrict__ out)
{
    extern __shared__ float sml[];
    ulonglong2* sw2 = (ulonglong2*)sml;     // [256][16] ulonglong2 = 64 KB
    float* hb = sml + 16384;                // [2][128] double-buffered h (16B-aligned)

    const int t = threadIdx.x;
    const int b = blockIdx.x;
    const int j = t >> 1;
    const int odd = t & 1;
    const int rowA = odd * 256 + j;
    const int rowB = rowA + 128;

    // load weights (packed)
    u64 wA2[64], wB2[32];
    {
        const float2* rA = (const float2*)(Whh + (size_t)rowA * 128);
        const float2* rB = (const float2*)(Whh + (size_t)rowB * 128);
#pragma unroll
        for (int m = 0; m < 64; m++) { float2 v = __ldg(&rA[m]); wA2[m] = pk2(v.x, v.y); }
#pragma unroll
        for (int m = 0; m < 32; m++) { float2 v = __ldg(&rB[m]); wB2[m] = pk2(v.x, v.y); }
        const float4* rB4 = (const float4*)rB;
#pragma unroll
        for (int q = 0; q < 16; q++) {
            float4 v = __ldg(&rB4[16 + q]);
            ulonglong2 w;
            w.x = pk2(v.x, v.y);
            w.y = pk2(v.z, v.w);
            sw2[t * 16 + ((q + t) & 15)] = w;
        }
    }
    if (t < 128) { hb[t] = 0.f; hb[128 + t] = 0.f; }
    float creg = 0.f;

    const float* xwp = g_xw + ((size_t)b * 1024) * 512;
    float x0 = __ldg(xwp + rowA);
    float x1 = __ldg(xwp + rowB);
    __syncthreads();

    for (int s = 0; s < 1024; s++) {
        float xv0 = x0, xv1 = x1;
        {   // prefetch next step's x projection (~1 step of latency cover)
            const float* nx = xwp + (size_t)((s < 1023) ? (s + 1) : s) * 512;
            x0 = __ldg(nx + rowA);
            x1 = __ldg(nx + rowB);
        }
        const int p = s & 1;
        const ulonglong2* h4 = (const ulonglong2*)(hb + p * 128);  // 32 pairs-of-pairs
        u64 A0 = 0ull, A1 = 0ull, B0 = 0ull, B1 = 0ull, C0 = 0ull, C1 = 0ull;
#pragma unroll
        for (int m = 0; m < 16; m++) {          // k = 0..63
            ulonglong2 hv = h4[m];
            fma2(A0, wA2[2 * m],     hv.x);
            fma2(A1, wA2[2 * m + 1], hv.y);
            fma2(B0, wB2[2 * m],     hv.x);
            fma2(B1, wB2[2 * m + 1], hv.y);
        }
#pragma unroll
        for (int q = 0; q < 16; q++) {          // k = 64..127
            ulonglong2 hv = h4[16 + q];
            ulonglong2 w  = sw2[t * 16 + ((q + t) & 15)];
            fma2(A0, wA2[32 + 2 * q], hv.x);
            fma2(A1, wA2[33 + 2 * q], hv.y);
            fma2(C0, w.x, hv.x);
            fma2(C1, w.y, hv.y);
        }
        float2 pa = up2(add2(A0, A1));
        float2 pb = up2(add2(add2(B0, B1), C0));
        float2 pc = up2(C1);
        float aA = pa.x + pa.y + xv0;              // even: i | odd: g
        float aB = pb.x + pb.y + pc.x + pc.y + xv1; // even: f | odd: o
        // activate own gates (odd lanes do tanh(g), sigm(o))
        float eA = odd ? tanhf_(aA) : sigmf_(aA);
        float eB = sigmf_(aB);
        // exchange activated values with lane neighbor
        float gv = __shfl_xor_sync(0xffffffffu, eA, 1);
        float ov = __shfl_xor_sync(0xffffffffu, eB, 1);
        if (!odd) {
            float c = eB * creg + eA * gv;   // f*c + i*g
            creg = c;
            float h = ov * tanhf_(c);
            hb[(p ^ 1) * 128 + j] = h;
            if (s == 1023) out[b * 128 + j] = h;
        }
        __syncthreads();
    }
}

// ------------------- launch -------------------
extern "C" void kernel_launch(void* const* d_in, const int* in_sizes, int n_in,
                              void* d_out, int out_size)
{
    int bi = (n_in >= 11) ? 1 : 0;   // batch_size scalar present or not
    const float* x   = (const float*)d_in[0];
    const ll*    ei  = (const ll*)   d_in[1];
    const float* W1  = (const float*)d_in[2 + bi];
    const float* b1  = (const float*)d_in[3 + bi];
    const float* W2  = (const float*)d_in[4 + bi];
    const float* b2  = (const float*)d_in[5 + bi];
    const float* Wih = (const float*)d_in[6 + bi];
    const float* Whh = (const float*)d_in[7 + bi];
    const float* bih = (const float*)d_in[8 + bi];
    const float* bhh = (const float*)d_in[9 + bi];
    float* out = (float*)d_out;

    const int smemG = 128 * 132 * 4 * 2;        // 135168 B
    const int smemL = 65536 + 2 * 128 * 4;      // 66560 B
    cudaFuncSetAttribute(k_gemm<0>, cudaFuncAttributeMaxDynamicSharedMemorySize, smemG);
    cudaFuncSetAttribute(k_gemm<1>, cudaFuncAttributeMaxDynamicSharedMemorySize, smemG);
    cudaFuncSetAttribute(k_gemm<2>, cudaFuncAttributeMaxDynamicSharedMemorySize, smemG);
    cudaFuncSetAttribute(k_lstm,    cudaFuncAttributeMaxDynamicSharedMemorySize, smemL);

    k_prep    <<<64, 1024>>>(bih, bhh, ei);
    k_hist    <<<NE / 256, 256>>>(ei);
    k_scan    <<<1, 1024>>>();
    k_scatter <<<NE / 256, 256>>>(ei);

    k_gemm<0><<<dim3(512, 1), 256, smemG>>>(x, W1);
    k_agg     <<<NN / 8, 256>>>(b1);
    k_gemm<1><<<dim3(512, 1), 256, smemG>>>(nullptr, W2);
    k_agg     <<<NN / 8, 256>>>(b2);
    k_gemm<2><<<dim3(512, 4), 256, smemG>>>(nullptr, Wih);
    k_lstm    <<<64, 256, smemL>>>(Whh, out);
    (void)in_sizes; (void)out_size;
}

// round 11
// speedup vs baseline: 1.1777x; 1.1777x over previous
#include <cuda_runtime.h>
#include <cstdint>

#define NN 65536
#define NE 1048576
typedef unsigned long long u64;
typedef long long ll;

// ------------------- device scratch (no allocation allowed) -------------------
__device__ __align__(16) float g_h  [(size_t)NN * 128];
__device__ __align__(16) float g_h2 [(size_t)NN * 128];
__device__ __align__(16) float g_agg[(size_t)NN * 128];
__device__ __align__(16) float g_xw [(size_t)NN * 512];
__device__ float g_dinv[NN];
__device__ float g_bias[512];
__device__ int   g_cnt[NN];
__device__ int   g_cur[NN];
__device__ int   g_indptr[NN + 1];
__device__ __align__(16) int2 g_csr[NE];
__device__ int   g_e32;       // 1 if edge_index is really int32

// ------------------- packed f32x2 helpers -------------------
__device__ __forceinline__ u64 pk2(float x, float y) {
    u64 r; asm("mov.b64 %0,{%1,%2};" : "=l"(r) : "f"(x), "f"(y)); return r;
}
__device__ __forceinline__ u64 pkdup(float x) {
    u64 r; asm("mov.b64 %0,{%1,%1};" : "=l"(r) : "f"(x)); return r;
}
__device__ __forceinline__ void fma2(u64 &d, u64 a, u64 b) {
    asm("fma.rn.f32x2 %0,%1,%2,%0;" : "+l"(d) : "l"(a), "l"(b));
}
__device__ __forceinline__ u64 add2(u64 a, u64 b) {
    u64 r; asm("add.rn.f32x2 %0,%1,%2;" : "=l"(r) : "l"(a), "l"(b)); return r;
}
__device__ __forceinline__ float2 up2(u64 v) {
    float2 r; asm("mov.b64 {%0,%1},%2;" : "=f"(r.x), "=f"(r.y) : "l"(v)); return r;
}

// ------------------- prep: zero + bias + dtype detect -------------------
__global__ __launch_bounds__(1024) void k_prep(const float* __restrict__ bi,
                                               const float* __restrict__ bh,
                                               const ll* __restrict__ ei) {
    int i = blockIdx.x * 1024 + threadIdx.x;
    if (i < NN) g_cnt[i] = 0;
    if (i < 512) g_bias[i] = bi[i] + bh[i];
    if (i == 0) {
        int bad = 0;
        for (int j = 0; j < 64; j++) {
            ll v = ei[j];
            if (v < 0 || v >= NN) bad = 1;
        }
        g_e32 = bad;
    }
}
__global__ __launch_bounds__(256) void k_hist(const ll* __restrict__ ei) {
    int e = blockIdx.x * 256 + threadIdx.x;
    if (e >= NE) return;
    int dst = g_e32 ? ((const int*)ei)[NE + e] : (int)ei[NE + e];
    atomicAdd(&g_cnt[dst], 1);
}
// scan + rsqrt fused (single block)
__global__ __launch_bounds__(1024) void k_scan() {
    __shared__ int ssum[1024];
    int t = threadIdx.x;
    int base = t * 64;
    int s = 0;
    const int4* c4 = (const int4*)&g_cnt[base];
    for (int i = 0; i < 16; i++) {
        int4 v = c4[i];
        s += v.x + v.y + v.z + v.w;
    }
    ssum[t] = s;
    __syncthreads();
    for (int off = 1; off < 1024; off <<= 1) {
        int add = (t >= off) ? ssum[t - off] : 0;
        __syncthreads();
        ssum[t] += add;
        __syncthreads();
    }
    int run = ssum[t] - s;   // exclusive prefix of this chunk
    for (int i = 0; i < 64; i++) {
        int c = g_cnt[base + i];
        g_indptr[base + i] = run;
        g_cur[base + i]    = run;
        g_dinv[base + i]   = rsqrtf(1.0f + (float)c);
        run += c;
    }
    if (t == 1023) g_indptr[NN] = run;
}
__global__ __launch_bounds__(256) void k_scatter(const ll* __restrict__ ei) {
    int e = blockIdx.x * 256 + threadIdx.x;
    if (e >= NE) return;
    int src, dst;
    if (g_e32) {
        const int* p = (const int*)ei;
        src = p[e]; dst = p[NE + e];
    } else {
        src = (int)ei[e]; dst = (int)ei[NE + e];
    }
    int pos = atomicAdd(&g_cur[dst], 1);
    float nm = g_dinv[src] * g_dinv[dst];
    g_csr[pos] = make_int2(src, __float_as_int(nm));
}

// ------------------- tiled GEMM (packed f32x2) -------------------
// MODE 0: g_h = x @ W1        (fused: g_agg = g_h * dinv^2)
// MODE 1: g_h = g_h2 @ W2     (same fusion)
// MODE 2: g_xw = g_h2 @ W_ih^T + (b_ih + b_hh)
template<int MODE>
__global__ __launch_bounds__(256)
void k_gemm(const float* __restrict__ Aext, const float* __restrict__ B)
{
    extern __shared__ float sm[];
    float* sB = sm;               // [128][132]  sB[k][n]
    float* sA = sm + 128 * 132;   // [128][132]  sA[k][r]  (A transposed)
    const float* A = (MODE == 0) ? Aext : g_h2;
    const int t = threadIdx.x;
    const int row0 = blockIdx.x * 128;
    const int col0 = (MODE == 2) ? blockIdx.y * 128 : 0;

    for (int idx = t; idx < 128 * 32; idx += 256) {
        int r = idx >> 5, k4 = idx & 31;
        float4 v = *(const float4*)&A[(size_t)(row0 + r) * 128 + k4 * 4];
        sA[(k4 * 4 + 0) * 132 + r] = v.x;
        sA[(k4 * 4 + 1) * 132 + r] = v.y;
        sA[(k4 * 4 + 2) * 132 + r] = v.z;
        sA[(k4 * 4 + 3) * 132 + r] = v.w;
    }
    if (MODE != 2) {
        for (int idx = t; idx < 128 * 32; idx += 256) {
            int k = idx >> 5, n4 = idx & 31;
            *(float4*)&sB[k * 132 + n4 * 4] = *(const float4*)&B[(size_t)k * 128 + n4 * 4];
        }
    } else {
        for (int idx = t; idx < 128 * 32; idx += 256) {
            int n = idx >> 5, k4 = idx & 31;
            float4 v = *(const float4*)&B[(size_t)(col0 + n) * 128 + k4 * 4];
            sB[(k4 * 4 + 0) * 132 + n] = v.x;
            sB[(k4 * 4 + 1) * 132 + n] = v.y;
            sB[(k4 * 4 + 2) * 132 + n] = v.z;
            sB[(k4 * 4 + 3) * 132 + n] = v.w;
        }
    }
    __syncthreads();

    const int warp = t >> 5, lane = t & 31;
    const int r0 = warp * 16;
    const int c0 = lane * 4;
    u64 acc[8][4];
#pragma unroll
    for (int i = 0; i < 8; i++)
#pragma unroll
        for (int c = 0; c < 4; c++) acc[i][c] = 0ull;

    for (int k = 0; k < 128; k++) {
        float4 bv = *(const float4*)&sB[k * 132 + c0];
        u64 b0 = pkdup(bv.x), b1 = pkdup(bv.y), b2 = pkdup(bv.z), b3 = pkdup(bv.w);
        const u64* ap = (const u64*)&sA[k * 132 + r0];
#pragma unroll
        for (int ii = 0; ii < 8; ii++) {
            u64 a = ap[ii];
            fma2(acc[ii][0], a, b0);
            fma2(acc[ii][1], a, b1);
            fma2(acc[ii][2], a, b2);
            fma2(acc[ii][3], a, b3);
        }
    }

    float4 bb = make_float4(0.f, 0.f, 0.f, 0.f);
    if (MODE == 2) bb = *(const float4*)&g_bias[col0 + c0];
#pragma unroll
    for (int ii = 0; ii < 8; ii++) {
        float2 u0 = up2(acc[ii][0]), u1 = up2(acc[ii][1]);
        float2 u2 = up2(acc[ii][2]), u3 = up2(acc[ii][3]);
        int rA = row0 + r0 + 2 * ii;
        float4 v0 = make_float4(u0.x + bb.x, u1.x + bb.y, u2.x + bb.z, u3.x + bb.w);
        float4 v1 = make_float4(u0.y + bb.x, u1.y + bb.y, u2.y + bb.z, u3.y + bb.w);
        if (MODE == 2) {
            *(float4*)&g_xw[(size_t)rA * 512 + col0 + c0] = v0;
            *(float4*)&g_xw[(size_t)(rA + 1) * 512 + col0 + c0] = v1;
        } else {
            *(float4*)&g_h[(size_t)rA * 128 + c0] = v0;
            *(float4*)&g_h[(size_t)(rA + 1) * 128 + c0] = v1;
            float d0 = g_dinv[rA];     float s0 = d0 * d0;
            float d1 = g_dinv[rA + 1]; float s1 = d1 * d1;
            float4 w0 = make_float4(v0.x * s0, v0.y * s0, v0.z * s0, v0.w * s0);
            float4 w1 = make_float4(v1.x * s1, v1.y * s1, v1.z * s1, v1.w * s1);
            *(float4*)&g_agg[(size_t)rA * 128 + c0] = w0;
            *(float4*)&g_agg[(size_t)(rA + 1) * 128 + c0] = w1;
        }
    }
}

// ------------------- edge aggregation: warp per node -------------------
__global__ __launch_bounds__(256)
void k_agg(const float* __restrict__ bias)
{
    int node = blockIdx.x * 8 + (threadIdx.x >> 5);
    if (node >= NN) return;
    int lane = threadIdx.x & 31;
    int s0 = g_indptr[node], s1 = g_indptr[node + 1];
    float4 acc = *(const float4*)&g_agg[(size_t)node * 128 + lane * 4];

    for (int e = s0; e < s1; e++) {
        int2 cur = __ldg(&g_csr[e]);
        float4 hv = __ldg((const float4*)&g_h[(size_t)cur.x * 128 + lane * 4]);
        float nm = __int_as_float(cur.y);
        acc.x += hv.x * nm; acc.y += hv.y * nm;
        acc.z += hv.z * nm; acc.w += hv.w * nm;
    }
    float4 bb = *(const float4*)&bias[lane * 4];
    float4 o;
    o.x = fmaxf(acc.x + bb.x, 0.f);
    o.y = fmaxf(acc.y + bb.y, 0.f);
    o.z = fmaxf(acc.z + bb.z, 0.f);
    o.w = fmaxf(acc.w + bb.w, 0.f);
    *(float4*)&g_h2[(size_t)node * 128 + lane * 4] = o;
}

// ------------------- LSTM: one CTA per batch, shuffle gate exchange -------------------
// Thread t -> unit j = t>>1. Even t owns rows j (i) and 128+j (f);
// odd t owns rows 256+j (g) and 384+j (o).  rowA = (t&1)*256 + j, rowB = rowA+128.
// rowA: all 128 weights in regs. rowB: k<64 in regs, k in [64,128) in smem.
// Smem weight slot permutation: slot = (q + t + 2*(t>>3)) & 15.
//   Bank of lane l's LDS.128 = 4*(slot mod 8) mod 32; the same-bank lane group
//   {l, l+8, l+16, l+24} gets slot-mod-8 offsets {0,2,4,6} -> distinct bank
//   quads; each 8-lane octet covers all 32 banks once -> CONFLICT-FREE
//   (the old (q+t)&15 was 4-way conflicted: 16 wavefronts per LDS.128).
// Gate partials exchanged lane<->lane via shfl.xor 1; h double-buffered in
// smem -> ONE barrier per step; c stays in a register.
__device__ __forceinline__ float sigmf_(float x) {
    return __fdividef(1.0f, 1.0f + __expf(-x));
}
__device__ __forceinline__ float tanhf_(float x) {
    float e = __expf(-2.0f * fabsf(x));            // in (0,1], no overflow
    return copysignf(__fdividef(1.0f - e, 1.0f + e), x);
}

__global__ __launch_bounds__(256, 1)
void k_lstm(const float* __restrict__ Whh, float* __restrict__ out)
{
    extern __shared__ float sml[];
    ulonglong2* sw2 = (ulonglong2*)sml;     // [256][16] ulonglong2 = 64 KB
    float* hb = sml + 16384;                // [2][128] double-buffered h

    const int t = threadIdx.x;
    const int b = blockIdx.x;
    const int j = t >> 1;
    const int odd = t & 1;
    const int rowA = odd * 256 + j;
    const int rowB = rowA + 128;
    const int sw_bias = t + 2 * (t >> 3);   // swizzle base (mod 16 applied per q)

    // load weights (packed)
    u64 wA2[64], wB2[32];
    {
        const float2* rA = (const float2*)(Whh + (size_t)rowA * 128);
        const float2* rB = (const float2*)(Whh + (size_t)rowB * 128);
#pragma unroll
        for (int m = 0; m < 64; m++) { float2 v = __ldg(&rA[m]); wA2[m] = pk2(v.x, v.y); }
#pragma unroll
        for (int m = 0; m < 32; m++) { float2 v = __ldg(&rB[m]); wB2[m] = pk2(v.x, v.y); }
        const float4* rB4 = (const float4*)rB;
#pragma unroll
        for (int q = 0; q < 16; q++) {
            float4 v = __ldg(&rB4[16 + q]);
            ulonglong2 w;
            w.x = pk2(v.x, v.y);
            w.y = pk2(v.z, v.w);
            sw2[t * 16 + ((q + sw_bias) & 15)] = w;
        }
    }
    if (t < 128) { hb[t] = 0.f; hb[128 + t] = 0.f; }
    float creg = 0.f;

    const float* xwp = g_xw + ((size_t)b * 1024) * 512;
    float x0 = __ldg(xwp + rowA);
    float x1 = __ldg(xwp + rowB);
    __syncthreads();

    for (int s = 0; s < 1024; s++) {
        float xv0 = x0, xv1 = x1;
        {   // prefetch next step's x projection
            const float* nx = xwp + (size_t)((s < 1023) ? (s + 1) : s) * 512;
            x0 = __ldg(nx + rowA);
            x1 = __ldg(nx + rowB);
        }
        const int p = s & 1;
        const u64* h2 = (const u64*)(hb + p * 128);
        u64 A0 = 0ull, A1 = 0ull, B0 = 0ull, B1 = 0ull, B2 = 0ull;
#pragma unroll
        for (int m = 0; m < 32; m++) {
            u64 hv = h2[m];
            fma2(A0, wA2[m], hv);
            fma2(B0, wB2[m], hv);
        }
#pragma unroll
        for (int m = 32; m < 64; m++) {
            u64 hv = h2[m];
            fma2(A1, wA2[m], hv);
        }
#pragma unroll
        for (int q = 0; q < 16; q++) {
            ulonglong2 w = sw2[t * 16 + ((q + sw_bias) & 15)];
            fma2(B1, w.x, h2[32 + 2 * q]);
            fma2(B2, w.y, h2[33 + 2 * q]);
        }
        float2 pa = up2(add2(A0, A1));
        float2 pb = up2(add2(add2(B0, B1), B2));
        float aA = pa.x + pa.y + xv0;    // even: gate i   | odd: gate g
        float aB = pb.x + pb.y + xv1;    // even: gate f   | odd: gate o
        // exchange with lane neighbor (same warp)
        float nA = __shfl_xor_sync(0xffffffffu, aA, 1);
        float nB = __shfl_xor_sync(0xffffffffu, aB, 1);
        if (!odd) {
            float iv = sigmf_(aA);
            float fv = sigmf_(aB);
            float gv = tanhf_(nA);
            float ov = sigmf_(nB);
            float c = fv * creg + iv * gv;
            creg = c;
            float h = ov * tanhf_(c);
            hb[(p ^ 1) * 128 + j] = h;
            if (s == 1023) out[b * 128 + j] = h;
        }
        __syncthreads();
    }
}

// ------------------- launch -------------------
extern "C" void kernel_launch(void* const* d_in, const int* in_sizes, int n_in,
                              void* d_out, int out_size)
{
    int bi = (n_in >= 11) ? 1 : 0;   // batch_size scalar present or not
    const float* x   = (const float*)d_in[0];
    const ll*    ei  = (const ll*)   d_in[1];
    const float* W1  = (const float*)d_in[2 + bi];
    const float* b1  = (const float*)d_in[3 + bi];
    const float* W2  = (const float*)d_in[4 + bi];
    const float* b2  = (const float*)d_in[5 + bi];
    const float* Wih = (const float*)d_in[6 + bi];
    const float* Whh = (const float*)d_in[7 + bi];
    const float* bih = (const float*)d_in[8 + bi];
    const float* bhh = (const float*)d_in[9 + bi];
    float* out = (float*)d_out;

    const int smemG = 128 * 132 * 4 * 2;        // 135168 B
    const int smemL = 65536 + 2 * 128 * 4;      // 66560 B
    cudaFuncSetAttribute(k_gemm<0>, cudaFuncAttributeMaxDynamicSharedMemorySize, smemG);
    cudaFuncSetAttribute(k_gemm<1>, cudaFuncAttributeMaxDynamicSharedMemorySize, smemG);
    cudaFuncSetAttribute(k_gemm<2>, cudaFuncAttributeMaxDynamicSharedMemorySize, smemG);
    cudaFuncSetAttribute(k_lstm,    cudaFuncAttributeMaxDynamicSharedMemorySize, smemL);

    // order: gemm0 before scatter (dependency-safe: gemm0 needs g_dinv from
    // k_scan; k_scatter only needed before k_agg) — shifts the ncu capture
    // window onto k_gemm<0> instead of k_scatter.
    k_prep    <<<64, 1024>>>(bih, bhh, ei);
    k_hist    <<<NE / 256, 256>>>(ei);
    k_scan    <<<1, 1024>>>();
    k_gemm<0><<<dim3(512, 1), 256, smemG>>>(x, W1);
    k_scatter <<<NE / 256, 256>>>(ei);
    k_agg     <<<NN / 8, 256>>>(b1);
    k_gemm<1><<<dim3(512, 1), 256, smemG>>>(nullptr, W2);
    k_agg     <<<NN / 8, 256>>>(b2);
    k_gemm<2><<<dim3(512, 4), 256, smemG>>>(nullptr, Wih);
    k_lstm    <<<64, 256, smemL>>>(Whh, out);
    (void)in_sizes; (void)out_size;
}

// round 12
// speedup vs baseline: 1.2008x; 1.0197x over previous
#include <cuda_runtime.h>
#include <cstdint>

#define NN 65536
#define NE 1048576
typedef unsigned long long u64;
typedef long long ll;

// ------------------- device scratch (no allocation allowed) -------------------
__device__ __align__(16) float g_h  [(size_t)NN * 128];
__device__ __align__(16) float g_h2 [(size_t)NN * 128];
__device__ __align__(16) float g_agg[(size_t)NN * 128];
__device__ __align__(16) float g_xw [(size_t)NN * 512];
__device__ float g_dinv[NN];
__device__ float g_bias[512];
__device__ int   g_cnt[NN];
__device__ int   g_cur[NN];
__device__ int   g_indptr[NN + 1];
__device__ __align__(16) int2 g_csr[NE];
__device__ int   g_e32;       // 1 if edge_index is really int32

// ------------------- packed f32x2 helpers -------------------
__device__ __forceinline__ u64 pk2(float x, float y) {
    u64 r; asm("mov.b64 %0,{%1,%2};" : "=l"(r) : "f"(x), "f"(y)); return r;
}
__device__ __forceinline__ u64 pkdup(float x) {
    u64 r; asm("mov.b64 %0,{%1,%1};" : "=l"(r) : "f"(x)); return r;
}
__device__ __forceinline__ void fma2(u64 &d, u64 a, u64 b) {
    asm("fma.rn.f32x2 %0,%1,%2,%0;" : "+l"(d) : "l"(a), "l"(b));
}
__device__ __forceinline__ u64 add2(u64 a, u64 b) {
    u64 r; asm("add.rn.f32x2 %0,%1,%2;" : "=l"(r) : "l"(a), "l"(b)); return r;
}
__device__ __forceinline__ float2 up2(u64 v) {
    float2 r; asm("mov.b64 {%0,%1},%2;" : "=f"(r.x), "=f"(r.y) : "l"(v)); return r;
}

// ------------------- prep: zero + bias + dtype detect -------------------
__global__ __launch_bounds__(1024) void k_prep(const float* __restrict__ bi,
                                               const float* __restrict__ bh,
                                               const ll* __restrict__ ei) {
    int i = blockIdx.x * 1024 + threadIdx.x;
    if (i < NN) g_cnt[i] = 0;
    if (i < 512) g_bias[i] = bi[i] + bh[i];
    if (i == 0) {
        int bad = 0;
        for (int j = 0; j < 64; j++) {
            ll v = ei[j];
            if (v < 0 || v >= NN) bad = 1;
        }
        g_e32 = bad;
    }
}
__global__ __launch_bounds__(256) void k_hist(const ll* __restrict__ ei) {
    int e = blockIdx.x * 256 + threadIdx.x;
    if (e >= NE) return;
    int dst = g_e32 ? ((const int*)ei)[NE + e] : (int)ei[NE + e];
    atomicAdd(&g_cnt[dst], 1);
}
// scan + rsqrt fused (single block)
__global__ __launch_bounds__(1024) void k_scan() {
    __shared__ int ssum[1024];
    int t = threadIdx.x;
    int base = t * 64;
    int s = 0;
    const int4* c4 = (const int4*)&g_cnt[base];
    for (int i = 0; i < 16; i++) {
        int4 v = c4[i];
        s += v.x + v.y + v.z + v.w;
    }
    ssum[t] = s;
    __syncthreads();
    for (int off = 1; off < 1024; off <<= 1) {
        int add = (t >= off) ? ssum[t - off] : 0;
        __syncthreads();
        ssum[t] += add;
        __syncthreads();
    }
    int run = ssum[t] - s;   // exclusive prefix of this chunk
    for (int i = 0; i < 64; i++) {
        int c = g_cnt[base + i];
        g_indptr[base + i] = run;
        g_cur[base + i]    = run;
        g_dinv[base + i]   = rsqrtf(1.0f + (float)c);
        run += c;
    }
    if (t == 1023) g_indptr[NN] = run;
}
__global__ __launch_bounds__(256) void k_scatter(const ll* __restrict__ ei) {
    int e = blockIdx.x * 256 + threadIdx.x;
    if (e >= NE) return;
    int src, dst;
    if (g_e32) {
        const int* p = (const int*)ei;
        src = p[e]; dst = p[NE + e];
    } else {
        src = (int)ei[e]; dst = (int)ei[NE + e];
    }
    int pos = atomicAdd(&g_cur[dst], 1);
    float nm = g_dinv[src] * g_dinv[dst];
    g_csr[pos] = make_int2(src, __float_as_int(nm));
}

// ------------------- tiled GEMM (packed f32x2, 512 threads) -------------------
// MODE 0: g_h = x @ W1        (fused: g_agg = g_h * dinv^2)
// MODE 1: g_h = g_h2 @ W2     (same fusion)
// MODE 2: g_xw = g_h2 @ W_ih^T + (b_ih + b_hh)
// 512 threads = 16 warps; warp owns 8 rows (4 row-pairs) x 128 cols.
template<int MODE>
__global__ __launch_bounds__(512)
void k_gemm(const float* __restrict__ Aext, const float* __restrict__ B)
{
    extern __shared__ float sm[];
    float* sB = sm;               // [128][132]  sB[k][n]
    float* sA = sm + 128 * 132;   // [128][132]  sA[k][r]  (A transposed)
    const float* A = (MODE == 0) ? Aext : g_h2;
    const int t = threadIdx.x;
    const int row0 = blockIdx.x * 128;
    const int col0 = (MODE == 2) ? blockIdx.y * 128 : 0;

    for (int idx = t; idx < 128 * 32; idx += 512) {
        int r = idx >> 5, k4 = idx & 31;
        float4 v = *(const float4*)&A[(size_t)(row0 + r) * 128 + k4 * 4];
        sA[(k4 * 4 + 0) * 132 + r] = v.x;
        sA[(k4 * 4 + 1) * 132 + r] = v.y;
        sA[(k4 * 4 + 2) * 132 + r] = v.z;
        sA[(k4 * 4 + 3) * 132 + r] = v.w;
    }
    if (MODE != 2) {
        for (int idx = t; idx < 128 * 32; idx += 512) {
            int k = idx >> 5, n4 = idx & 31;
            *(float4*)&sB[k * 132 + n4 * 4] = *(const float4*)&B[(size_t)k * 128 + n4 * 4];
        }
    } else {
        for (int idx = t; idx < 128 * 32; idx += 512) {
            int n = idx >> 5, k4 = idx & 31;
            float4 v = *(const float4*)&B[(size_t)(col0 + n) * 128 + k4 * 4];
            sB[(k4 * 4 + 0) * 132 + n] = v.x;
            sB[(k4 * 4 + 1) * 132 + n] = v.y;
            sB[(k4 * 4 + 2) * 132 + n] = v.z;
            sB[(k4 * 4 + 3) * 132 + n] = v.w;
        }
    }
    __syncthreads();

    const int warp = t >> 5, lane = t & 31;
    const int r0 = warp * 8;     // 16 warps x 8 rows = 128 rows
    const int c0 = lane * 4;     // 32 lanes x 4 cols
    u64 acc[4][4];
#pragma unroll
    for (int i = 0; i < 4; i++)
#pragma unroll
        for (int c = 0; c < 4; c++) acc[i][c] = 0ull;

#pragma unroll 2
    for (int k = 0; k < 128; k++) {
        float4 bv = *(const float4*)&sB[k * 132 + c0];
        u64 b0 = pkdup(bv.x), b1 = pkdup(bv.y), b2 = pkdup(bv.z), b3 = pkdup(bv.w);
        const u64* ap = (const u64*)&sA[k * 132 + r0];
#pragma unroll
        for (int ii = 0; ii < 4; ii++) {
            u64 a = ap[ii];
            fma2(acc[ii][0], a, b0);
            fma2(acc[ii][1], a, b1);
            fma2(acc[ii][2], a, b2);
            fma2(acc[ii][3], a, b3);
        }
    }

    float4 bb = make_float4(0.f, 0.f, 0.f, 0.f);
    if (MODE == 2) bb = *(const float4*)&g_bias[col0 + c0];
#pragma unroll
    for (int ii = 0; ii < 4; ii++) {
        float2 u0 = up2(acc[ii][0]), u1 = up2(acc[ii][1]);
        float2 u2 = up2(acc[ii][2]), u3 = up2(acc[ii][3]);
        int rA = row0 + r0 + 2 * ii;
        float4 v0 = make_float4(u0.x + bb.x, u1.x + bb.y, u2.x + bb.z, u3.x + bb.w);
        float4 v1 = make_float4(u0.y + bb.x, u1.y + bb.y, u2.y + bb.z, u3.y + bb.w);
        if (MODE == 2) {
            *(float4*)&g_xw[(size_t)rA * 512 + col0 + c0] = v0;
            *(float4*)&g_xw[(size_t)(rA + 1) * 512 + col0 + c0] = v1;
        } else {
            *(float4*)&g_h[(size_t)rA * 128 + c0] = v0;
            *(float4*)&g_h[(size_t)(rA + 1) * 128 + c0] = v1;
            float d0 = g_dinv[rA];     float s0 = d0 * d0;
            float d1 = g_dinv[rA + 1]; float s1 = d1 * d1;
            float4 w0 = make_float4(v0.x * s0, v0.y * s0, v0.z * s0, v0.w * s0);
            float4 w1 = make_float4(v1.x * s1, v1.y * s1, v1.z * s1, v1.w * s1);
            *(float4*)&g_agg[(size_t)rA * 128 + c0] = w0;
            *(float4*)&g_agg[(size_t)(rA + 1) * 128 + c0] = w1;
        }
    }
}

// ------------------- edge aggregation: warp per node -------------------
__global__ __launch_bounds__(256)
void k_agg(const float* __restrict__ bias)
{
    int node = blockIdx.x * 8 + (threadIdx.x >> 5);
    if (node >= NN) return;
    int lane = threadIdx.x & 31;
    int s0 = g_indptr[node], s1 = g_indptr[node + 1];
    float4 acc = *(const float4*)&g_agg[(size_t)node * 128 + lane * 4];

    for (int e = s0; e < s1; e++) {
        int2 cur = __ldg(&g_csr[e]);
        float4 hv = __ldg((const float4*)&g_h[(size_t)cur.x * 128 + lane * 4]);
        float nm = __int_as_float(cur.y);
        acc.x += hv.x * nm; acc.y += hv.y * nm;
        acc.z += hv.z * nm; acc.w += hv.w * nm;
    }
    float4 bb = *(const float4*)&bias[lane * 4];
    float4 o;
    o.x = fmaxf(acc.x + bb.x, 0.f);
    o.y = fmaxf(acc.y + bb.y, 0.f);
    o.z = fmaxf(acc.z + bb.z, 0.f);
    o.w = fmaxf(acc.w + bb.w, 0.f);
    *(float4*)&g_h2[(size_t)node * 128 + lane * 4] = o;
}

// ------------------- LSTM: one CTA per batch, shuffle gate exchange -------------------
// Same structure as the 1648-us baseline; ONLY change: h read via broadcast
// LDS.128 (ulonglong2) feeding the identical 5-chain FMA2 body.
__device__ __forceinline__ float sigmf_(float x) {
    return __fdividef(1.0f, 1.0f + __expf(-x));
}
__device__ __forceinline__ float tanhf_(float x) {
    float e = __expf(-2.0f * fabsf(x));            // in (0,1], no overflow
    return copysignf(__fdividef(1.0f - e, 1.0f + e), x);
}

__global__ __launch_bounds__(256, 1)
void k_lstm(const float* __restrict__ Whh, float* __restrict__ out)
{
    extern __shared__ float sml[];
    ulonglong2* sw2 = (ulonglong2*)sml;     // [256][16] ulonglong2 = 64 KB
    float* hb = sml + 16384;                // [2][128] double-buffered h (16B-aligned)

    const int t = threadIdx.x;
    const int b = blockIdx.x;
    const int j = t >> 1;
    const int odd = t & 1;
    const int rowA = odd * 256 + j;
    const int rowB = rowA + 128;
    const int sw_bias = t + 2 * (t >> 3);

    // load weights (packed)
    u64 wA2[64], wB2[32];
    {
        const float2* rA = (const float2*)(Whh + (size_t)rowA * 128);
        const float2* rB = (const float2*)(Whh + (size_t)rowB * 128);
#pragma unroll
        for (int m = 0; m < 64; m++) { float2 v = __ldg(&rA[m]); wA2[m] = pk2(v.x, v.y); }
#pragma unroll
        for (int m = 0; m < 32; m++) { float2 v = __ldg(&rB[m]); wB2[m] = pk2(v.x, v.y); }
        const float4* rB4 = (const float4*)rB;
#pragma unroll
        for (int q = 0; q < 16; q++) {
            float4 v = __ldg(&rB4[16 + q]);
            ulonglong2 w;
            w.x = pk2(v.x, v.y);
            w.y = pk2(v.z, v.w);
            sw2[t * 16 + ((q + sw_bias) & 15)] = w;
        }
    }
    if (t < 128) { hb[t] = 0.f; hb[128 + t] = 0.f; }
    float creg = 0.f;

    const float* xwp = g_xw + ((size_t)b * 1024) * 512;
    float x0 = __ldg(xwp + rowA);
    float x1 = __ldg(xwp + rowB);
    __syncthreads();

    for (int s = 0; s < 1024; s++) {
        float xv0 = x0, xv1 = x1;
        {   // prefetch next step's x projection
            const float* nx = xwp + (size_t)((s < 1023) ? (s + 1) : s) * 512;
            x0 = __ldg(nx + rowA);
            x1 = __ldg(nx + rowB);
        }
        const int p = s & 1;
        const ulonglong2* h4 = (const ulonglong2*)(hb + p * 128);
        u64 A0 = 0ull, A1 = 0ull, B0 = 0ull, B1 = 0ull, B2 = 0ull;
#pragma unroll
        for (int m = 0; m < 16; m++) {          // k = 0..63 (LDS.128 broadcast)
            ulonglong2 hv = h4[m];
            fma2(A0, wA2[2 * m],     hv.x);
            fma2(B0, wB2[2 * m],     hv.x);
            fma2(A0, wA2[2 * m + 1], hv.y);
            fma2(B0, wB2[2 * m + 1], hv.y);
        }
#pragma unroll
        for (int m = 16; m < 32; m++) {         // k = 64..127 for rowA
            ulonglong2 hv = h4[m];
            fma2(A1, wA2[2 * m],     hv.x);
            fma2(A1, wA2[2 * m + 1], hv.y);
        }
#pragma unroll
        for (int q = 0; q < 16; q++) {          // k = 64..127 for rowB (smem weights)
            ulonglong2 w = sw2[t * 16 + ((q + sw_bias) & 15)];
            ulonglong2 hv = h4[16 + q];
            fma2(B1, w.x, hv.x);
            fma2(B2, w.y, hv.y);
        }
        float2 pa = up2(add2(A0, A1));
        float2 pb = up2(add2(add2(B0, B1), B2));
        float aA = pa.x + pa.y + xv0;    // even: gate i   | odd: gate g
        float aB = pb.x + pb.y + xv1;    // even: gate f   | odd: gate o
        float nA = __shfl_xor_sync(0xffffffffu, aA, 1);
        float nB = __shfl_xor_sync(0xffffffffu, aB, 1);
        if (!odd) {
            float iv = sigmf_(aA);
            float fv = sigmf_(aB);
            float gv = tanhf_(nA);
            float ov = sigmf_(nB);
            float c = fv * creg + iv * gv;
            creg = c;
            float h = ov * tanhf_(c);
            hb[(p ^ 1) * 128 + j] = h;
            if (s == 1023) out[b * 128 + j] = h;
        }
        __syncthreads();
    }
}

// ------------------- launch -------------------
extern "C" void kernel_launch(void* const* d_in, const int* in_sizes, int n_in,
                              void* d_out, int out_size)
{
    int bi = (n_in >= 11) ? 1 : 0;   // batch_size scalar present or not
    const float* x   = (const float*)d_in[0];
    const ll*    ei  = (const ll*)   d_in[1];
    const float* W1  = (const float*)d_in[2 + bi];
    const float* b1  = (const float*)d_in[3 + bi];
    const float* W2  = (const float*)d_in[4 + bi];
    const float* b2  = (const float*)d_in[5 + bi];
    const float* Wih = (const float*)d_in[6 + bi];
    const float* Whh = (const float*)d_in[7 + bi];
    const float* bih = (const float*)d_in[8 + bi];
    const float* bhh = (const float*)d_in[9 + bi];
    float* out = (float*)d_out;

    const int smemG = 128 * 132 * 4 * 2;        // 135168 B
    const int smemL = 65536 + 2 * 128 * 4;      // 66560 B
    cudaFuncSetAttribute(k_gemm<0>, cudaFuncAttributeMaxDynamicSharedMemorySize, smemG);
    cudaFuncSetAttribute(k_gemm<1>, cudaFuncAttributeMaxDynamicSharedMemorySize, smemG);
    cudaFuncSetAttribute(k_gemm<2>, cudaFuncAttributeMaxDynamicSharedMemorySize, smemG);
    cudaFuncSetAttribute(k_lstm,    cudaFuncAttributeMaxDynamicSharedMemorySize, smemL);

    k_prep    <<<64, 1024>>>(bih, bhh, ei);
    k_hist    <<<NE / 256, 256>>>(ei);
    k_scan    <<<1, 1024>>>();
    k_gemm<0><<<dim3(512, 1), 512, smemG>>>(x, W1);
    k_scatter <<<NE / 256, 256>>>(ei);
    k_agg     <<<NN / 8, 256>>>(b1);
    k_gemm<1><<<dim3(512, 1), 512, smemG>>>(nullptr, W2);
    k_agg     <<<NN / 8, 256>>>(b2);
    k_gemm<2><<<dim3(512, 4), 512, smemG>>>(nullptr, Wih);
    k_lstm    <<<64, 256, smemL>>>(Whh, out);
    (void)in_sizes; (void)out_size;
}

// round 14
// speedup vs baseline: 1.2606x; 1.0498x over previous
#include <cuda_runtime.h>
#include <cstdint>

#define NN 65536
#define NE 1048576
typedef unsigned long long u64;
typedef long long ll;

// ------------------- device scratch (no allocation allowed) -------------------
__device__ __align__(16) float g_h  [(size_t)NN * 128];
__device__ __align__(16) float g_h2 [(size_t)NN * 128];
__device__ __align__(16) float g_agg[(size_t)NN * 128];
__device__ __align__(16) float g_xw [(size_t)NN * 512];
__device__ float g_dinv[NN];
__device__ float g_bias[512];
__device__ int   g_cnt[NN];
__device__ int   g_cur[NN];
__device__ int   g_indptr[NN + 1];
__device__ __align__(16) int2 g_csr[NE];
__device__ int   g_e32;       // 1 if edge_index is really int32

// ------------------- packed f32x2 helpers -------------------
__device__ __forceinline__ u64 pk2(float x, float y) {
    u64 r; asm("mov.b64 %0,{%1,%2};" : "=l"(r) : "f"(x), "f"(y)); return r;
}
__device__ __forceinline__ u64 pkdup(float x) {
    u64 r; asm("mov.b64 %0,{%1,%1};" : "=l"(r) : "f"(x)); return r;
}
__device__ __forceinline__ void fma2(u64 &d, u64 a, u64 b) {
    asm("fma.rn.f32x2 %0,%1,%2,%0;" : "+l"(d) : "l"(a), "l"(b));
}
__device__ __forceinline__ u64 add2(u64 a, u64 b) {
    u64 r; asm("add.rn.f32x2 %0,%1,%2;" : "=l"(r) : "l"(a), "l"(b)); return r;
}
__device__ __forceinline__ float2 up2(u64 v) {
    float2 r; asm("mov.b64 {%0,%1},%2;" : "=f"(r.x), "=f"(r.y) : "l"(v)); return r;
}

// ------------------- prep: zero + bias + dtype detect -------------------
__global__ __launch_bounds__(1024) void k_prep(const float* __restrict__ bi,
                                               const float* __restrict__ bh,
                                               const ll* __restrict__ ei) {
    int i = blockIdx.x * 1024 + threadIdx.x;
    if (i < NN) g_cnt[i] = 0;
    if (i < 512) g_bias[i] = bi[i] + bh[i];
    if (i == 0) {
        int bad = 0;
        for (int j = 0; j < 64; j++) {
            ll v = ei[j];
            if (v < 0 || v >= NN) bad = 1;
        }
        g_e32 = bad;
    }
}
__global__ __launch_bounds__(256) void k_hist(const ll* __restrict__ ei) {
    int e = blockIdx.x * 256 + threadIdx.x;
    if (e >= NE) return;
    int dst = g_e32 ? ((const int*)ei)[NE + e] : (int)ei[NE + e];
    atomicAdd(&g_cnt[dst], 1);
}
// scan + rsqrt fused (single block)
__global__ __launch_bounds__(1024) void k_scan() {
    __shared__ int ssum[1024];
    int t = threadIdx.x;
    int base = t * 64;
    int s = 0;
    const int4* c4 = (const int4*)&g_cnt[base];
    for (int i = 0; i < 16; i++) {
        int4 v = c4[i];
        s += v.x + v.y + v.z + v.w;
    }
    ssum[t] = s;
    __syncthreads();
    for (int off = 1; off < 1024; off <<= 1) {
        int add = (t >= off) ? ssum[t - off] : 0;
        __syncthreads();
        ssum[t] += add;
        __syncthreads();
    }
    int run = ssum[t] - s;   // exclusive prefix of this chunk
    for (int i = 0; i < 64; i++) {
        int c = g_cnt[base + i];
        g_indptr[base + i] = run;
        g_cur[base + i]    = run;
        g_dinv[base + i]   = rsqrtf(1.0f + (float)c);
        run += c;
    }
    if (t == 1023) g_indptr[NN] = run;
}
__global__ __launch_bounds__(256) void k_scatter(const ll* __restrict__ ei) {
    int e = blockIdx.x * 256 + threadIdx.x;
    if (e >= NE) return;
    int src, dst;
    if (g_e32) {
        const int* p = (const int*)ei;
        src = p[e]; dst = p[NE + e];
    } else {
        src = (int)ei[e]; dst = (int)ei[NE + e];
    }
    int pos = atomicAdd(&g_cur[dst], 1);
    float nm = g_dinv[src] * g_dinv[dst];
    g_csr[pos] = make_int2(src, __float_as_int(nm));
}

// ------------------- tiled GEMM (packed f32x2, 512 thr, 2 CTA/SM) -------------------
// MODE 0: g_h = x @ W1        (fused: g_agg = g_h * dinv^2)
// MODE 1: g_h = g_h2 @ W2     (same fusion)
// MODE 2: g_xw = g_h2 @ W_ih^T + (b_ih + b_hh)
// smem: sB full (128k x 128n, pad 132) + sA half-k (64k x 128r, pad 130),
// staged twice -> 100.9 KB total -> 2 CTAs/SM, 32 warps.
#define SB_ELEMS (128 * 132)
#define SA_ELEMS (64 * 130)
template<int MODE>
__global__ __launch_bounds__(512, 2)
void k_gemm(const float* __restrict__ Aext, const float* __restrict__ B)
{
    extern __shared__ float sm[];
    float* sB = sm;               // [128][132]  sB[k][n]
    float* sA = sm + SB_ELEMS;    // [64][130]   sA[kk][r] (half-k, A transposed)
    const float* A = (MODE == 0) ? Aext : g_h2;
    const int t = threadIdx.x;
    const int row0 = blockIdx.x * 128;
    const int col0 = (MODE == 2) ? blockIdx.y * 128 : 0;

    // stage B tile (full k)
    if (MODE != 2) {
        for (int idx = t; idx < 128 * 32; idx += 512) {
            int k = idx >> 5, n4 = idx & 31;
            *(float4*)&sB[k * 132 + n4 * 4] = *(const float4*)&B[(size_t)k * 128 + n4 * 4];
        }
    } else {
        for (int idx = t; idx < 128 * 32; idx += 512) {
            int n = idx >> 5, k4 = idx & 31;
            float4 v = *(const float4*)&B[(size_t)(col0 + n) * 128 + k4 * 4];
            sB[(k4 * 4 + 0) * 132 + n] = v.x;
            sB[(k4 * 4 + 1) * 132 + n] = v.y;
            sB[(k4 * 4 + 2) * 132 + n] = v.z;
            sB[(k4 * 4 + 3) * 132 + n] = v.w;
        }
    }

    const int warp = t >> 5, lane = t & 31;
    const int r0 = warp * 8;     // 16 warps x 8 rows = 128 rows
    const int c0 = lane * 4;     // 32 lanes x 4 cols
    u64 acc[4][4];
#pragma unroll
    for (int i = 0; i < 4; i++)
#pragma unroll
        for (int c = 0; c < 4; c++) acc[i][c] = 0ull;

#pragma unroll 1
    for (int half = 0; half < 2; half++) {
        // stage A half-tile transposed: sA[kk][r] = A[row0+r][half*64+kk]
        for (int idx = t; idx < 128 * 16; idx += 512) {
            int r = idx >> 4, k4 = idx & 15;
            float4 v = *(const float4*)&A[(size_t)(row0 + r) * 128 + half * 64 + k4 * 4];
            sA[(k4 * 4 + 0) * 130 + r] = v.x;
            sA[(k4 * 4 + 1) * 130 + r] = v.y;
            sA[(k4 * 4 + 2) * 130 + r] = v.z;
            sA[(k4 * 4 + 3) * 130 + r] = v.w;
        }
        __syncthreads();   // (also covers sB on first pass)

#pragma unroll 2
        for (int kk = 0; kk < 64; kk++) {
            int k = half * 64 + kk;
            float4 bv = *(const float4*)&sB[k * 132 + c0];
            u64 b0 = pkdup(bv.x), b1 = pkdup(bv.y), b2 = pkdup(bv.z), b3 = pkdup(bv.w);
            const u64* ap = (const u64*)&sA[kk * 130 + r0];
#pragma unroll
            for (int ii = 0; ii < 4; ii++) {
                u64 a = ap[ii];
                fma2(acc[ii][0], a, b0);
                fma2(acc[ii][1], a, b1);
                fma2(acc[ii][2], a, b2);
                fma2(acc[ii][3], a, b3);
            }
        }
        __syncthreads();   // before overwriting sA
    }

    float4 bb = make_float4(0.f, 0.f, 0.f, 0.f);
    if (MODE == 2) bb = *(const float4*)&g_bias[col0 + c0];
#pragma unroll
    for (int ii = 0; ii < 4; ii++) {
        float2 u0 = up2(acc[ii][0]), u1 = up2(acc[ii][1]);
        float2 u2 = up2(acc[ii][2]), u3 = up2(acc[ii][3]);
        int rA = row0 + r0 + 2 * ii;
        float4 v0 = make_float4(u0.x + bb.x, u1.x + bb.y, u2.x + bb.z, u3.x + bb.w);
        float4 v1 = make_float4(u0.y + bb.x, u1.y + bb.y, u2.y + bb.z, u3.y + bb.w);
        if (MODE == 2) {
            *(float4*)&g_xw[(size_t)rA * 512 + col0 + c0] = v0;
            *(float4*)&g_xw[(size_t)(rA + 1) * 512 + col0 + c0] = v1;
        } else {
            *(float4*)&g_h[(size_t)rA * 128 + c0] = v0;
            *(float4*)&g_h[(size_t)(rA + 1) * 128 + c0] = v1;
            float d0 = g_dinv[rA];     float s0 = d0 * d0;
            float d1 = g_dinv[rA + 1]; float s1 = d1 * d1;
            float4 w0 = make_float4(v0.x * s0, v0.y * s0, v0.z * s0, v0.w * s0);
            float4 w1 = make_float4(v1.x * s1, v1.y * s1, v1.z * s1, v1.w * s1);
            *(float4*)&g_agg[(size_t)rA * 128 + c0] = w0;
            *(float4*)&g_agg[(size_t)(rA + 1) * 128 + c0] = w1;
        }
    }
}

// ------------------- edge aggregation: warp per node -------------------
__global__ __launch_bounds__(256)
void k_agg(const float* __restrict__ bias)
{
    int node = blockIdx.x * 8 + (threadIdx.x >> 5);
    if (node >= NN) return;
    int lane = threadIdx.x & 31;
    int s0 = g_indptr[node], s1 = g_indptr[node + 1];
    float4 acc = *(const float4*)&g_agg[(size_t)node * 128 + lane * 4];

    for (int e = s0; e < s1; e++) {
        int2 cur = __ldg(&g_csr[e]);
        float4 hv = __ldg((const float4*)&g_h[(size_t)cur.x * 128 + lane * 4]);
        float nm = __int_as_float(cur.y);
        acc.x += hv.x * nm; acc.y += hv.y * nm;
        acc.z += hv.z * nm; acc.w += hv.w * nm;
    }
    float4 bb = *(const float4*)&bias[lane * 4];
    float4 o;
    o.x = fmaxf(acc.x + bb.x, 0.f);
    o.y = fmaxf(acc.y + bb.y, 0.f);
    o.z = fmaxf(acc.z + bb.z, 0.f);
    o.w = fmaxf(acc.w + bb.w, 0.f);
    *(float4*)&g_h2[(size_t)node * 128 + lane * 4] = o;
}

// ------------------- LSTM: one CTA per batch (R10 body — best known) -------------------
__device__ __forceinline__ float sigmf_(float x) {
    return __fdividef(1.0f, 1.0f + __expf(-x));
}
__device__ __forceinline__ float tanhf_(float x) {
    float e = __expf(-2.0f * fabsf(x));            // in (0,1], no overflow
    return copysignf(__fdividef(1.0f - e, 1.0f + e), x);
}

__global__ __launch_bounds__(256, 1)
void k_lstm(const float* __restrict__ Whh, float* __restrict__ out)
{
    extern __shared__ float sml[];
    ulonglong2* sw2 = (ulonglong2*)sml;     // [256][16] ulonglong2 = 64 KB
    float* hb = sml + 16384;                // [2][128] double-buffered h

    const int t = threadIdx.x;
    const int b = blockIdx.x;
    const int j = t >> 1;
    const int odd = t & 1;
    const int rowA = odd * 256 + j;
    const int rowB = rowA + 128;
    const int sw_bias = t + 2 * (t >> 3);   // swizzle base (mod 16 applied per q)

    // load weights (packed)
    u64 wA2[64], wB2[32];
    {
        const float2* rA = (const float2*)(Whh + (size_t)rowA * 128);
        const float2* rB = (const float2*)(Whh + (size_t)rowB * 128);
#pragma unroll
        for (int m = 0; m < 64; m++) { float2 v = __ldg(&rA[m]); wA2[m] = pk2(v.x, v.y); }
#pragma unroll
        for (int m = 0; m < 32; m++) { float2 v = __ldg(&rB[m]); wB2[m] = pk2(v.x, v.y); }
        const float4* rB4 = (const float4*)rB;
#pragma unroll
        for (int q = 0; q < 16; q++) {
            float4 v = __ldg(&rB4[16 + q]);
            ulonglong2 w;
            w.x = pk2(v.x, v.y);
            w.y = pk2(v.z, v.w);
            sw2[t * 16 + ((q + sw_bias) & 15)] = w;
        }
    }
    if (t < 128) { hb[t] = 0.f; hb[128 + t] = 0.f; }
    float creg = 0.f;

    const float* xwp = g_xw + ((size_t)b * 1024) * 512;
    float x0 = __ldg(xwp + rowA);
    float x1 = __ldg(xwp + rowB);
    __syncthreads();

    for (int s = 0; s < 1024; s++) {
        float xv0 = x0, xv1 = x1;
        {   // prefetch next step's x projection
            const float* nx = xwp + (size_t)((s < 1023) ? (s + 1) : s) * 512;
            x0 = __ldg(nx + rowA);
            x1 = __ldg(nx + rowB);
        }
        const int p = s & 1;
        const u64* h2 = (const u64*)(hb + p * 128);
        u64 A0 = 0ull, A1 = 0ull, B0 = 0ull, B1 = 0ull, B2 = 0ull;
#pragma unroll
        for (int m = 0; m < 32; m++) {
            u64 hv = h2[m];
            fma2(A0, wA2[m], hv);
            fma2(B0, wB2[m], hv);
        }
#pragma unroll
        for (int m = 32; m < 64; m++) {
            u64 hv = h2[m];
            fma2(A1, wA2[m], hv);
        }
#pragma unroll
        for (int q = 0; q < 16; q++) {
            ulonglong2 w = sw2[t * 16 + ((q + sw_bias) & 15)];
            fma2(B1, w.x, h2[32 + 2 * q]);
            fma2(B2, w.y, h2[33 + 2 * q]);
        }
        float2 pa = up2(add2(A0, A1));
        float2 pb = up2(add2(add2(B0, B1), B2));
        float aA = pa.x + pa.y + xv0;    // even: gate i   | odd: gate g
        float aB = pb.x + pb.y + xv1;    // even: gate f   | odd: gate o
        float nA = __shfl_xor_sync(0xffffffffu, aA, 1);
        float nB = __shfl_xor_sync(0xffffffffu, aB, 1);
        if (!odd) {
            float iv = sigmf_(aA);
            float fv = sigmf_(aB);
            float gv = tanhf_(nA);
            float ov = sigmf_(nB);
            float c = fv * creg + iv * gv;
            creg = c;
            float h = ov * tanhf_(c);
            hb[(p ^ 1) * 128 + j] = h;
            if (s == 1023) out[b * 128 + j] = h;
        }
        __syncthreads();
    }
}

// ------------------- launch -------------------
extern "C" void kernel_launch(void* const* d_in, const int* in_sizes, int n_in,
                              void* d_out, int out_size)
{
    int bi = (n_in >= 11) ? 1 : 0;   // batch_size scalar present or not
    const float* x   = (const float*)d_in[0];
    const ll*    ei  = (const ll*)   d_in[1];
    const float* W1  = (const float*)d_in[2 + bi];
    const float* b1  = (const float*)d_in[3 + bi];
    const float* W2  = (const float*)d_in[4 + bi];
    const float* b2  = (const float*)d_in[5 + bi];
    const float* Wih = (const float*)d_in[6 + bi];
    const float* Whh = (const float*)d_in[7 + bi];
    const float* bih = (const float*)d_in[8 + bi];
    const float* bhh = (const float*)d_in[9 + bi];
    float* out = (float*)d_out;

    const int smemG = (SB_ELEMS + SA_ELEMS) * 4;   // 100864 B -> 2 CTA/SM
    const int smemL = 65536 + 2 * 128 * 4;         // 66560 B
    cudaFuncSetAttribute(k_gemm<0>, cudaFuncAttributeMaxDynamicSharedMemorySize, smemG);
    cudaFuncSetAttribute(k_gemm<1>, cudaFuncAttributeMaxDynamicSharedMemorySize, smemG);
    cudaFuncSetAttribute(k_gemm<2>, cudaFuncAttributeMaxDynamicSharedMemorySize, smemG);
    cudaFuncSetAttribute(k_lstm,    cudaFuncAttributeMaxDynamicSharedMemorySize, smemL);

    k_prep    <<<64, 1024>>>(bih, bhh, ei);
    k_hist    <<<NE / 256, 256>>>(ei);
    k_scan    <<<1, 1024>>>();
    k_gemm<0><<<dim3(512, 1), 512, smemG>>>(x, W1);
    k_scatter <<<NE / 256, 256>>>(ei);
    k_agg     <<<NN / 8, 256>>>(b1);
    k_gemm<1><<<dim3(512, 1), 512, smemG>>>(nullptr, W2);
    k_agg     <<<NN / 8, 256>>>(b2);
    k_gemm<2><<<dim3(512, 4), 512, smemG>>>(nullptr, Wih);
    k_lstm    <<<64, 256, smemL>>>(Whh, out);
    (void)in_sizes; (void)out_size;
}